// round 1
// baseline (speedup 1.0000x reference)
#include <cuda_runtime.h>
#include <math.h>

// Problem constants
constexpr int N  = 8192;
constexpr int D  = 256;
constexpr float EPS = 1e-12f;

// GEMM tiling
constexpr int BM = 128;
constexpr int BN = 128;
constexpr int BK = 16;
constexpr int TM = 8;
constexpr int TN = 8;
constexpr int SMEM_STRIDE = 132;   // padded BM/BN stride (multiple of 4 for LDS.128, offset-4 banks for stores)

// Scratch: row squared-norms (allocation-free rule -> __device__ global)
__device__ float g_sq[N];

// ---------------------------------------------------------------------------
// Kernel 1: sq[i] = sum_k x[i][k]^2   (one warp per row, float4 loads)
// ---------------------------------------------------------------------------
__global__ void row_sq_kernel(const float* __restrict__ x) {
    int warp = (blockIdx.x * blockDim.x + threadIdx.x) >> 5;
    int lane = threadIdx.x & 31;
    if (warp >= N) return;
    const float4* p = reinterpret_cast<const float4*>(x + (size_t)warp * D);
    float4 a = p[lane];        // 64 float4 per row: lane and lane+32
    float4 b = p[lane + 32];
    float s = a.x*a.x + a.y*a.y + a.z*a.z + a.w*a.w
            + b.x*b.x + b.y*b.y + b.z*b.z + b.w*b.w;
    #pragma unroll
    for (int off = 16; off > 0; off >>= 1)
        s += __shfl_xor_sync(0xffffffffu, s, off);
    if (lane == 0) g_sq[warp] = s;
}

// ---------------------------------------------------------------------------
// Kernel 2: fused  out[i][j] = 1 - sigmoid((sqrt(max(sq_i+sq_j-2*dot, EPS)) + thr)*t)
// Classic fp32 SGEMM: 128x128 block tile, 8x8 per-thread tile, BK=16.
// ---------------------------------------------------------------------------
__global__ void __launch_bounds__(256, 2)
dist_sigmoid_kernel(const float* __restrict__ x,
                    const float* __restrict__ thr_p,
                    const float* __restrict__ t_p,
                    float* __restrict__ out)
{
    __shared__ float As[BK][SMEM_STRIDE];
    __shared__ float Bs[BK][SMEM_STRIDE];

    const int tid = threadIdx.x;     // 0..255
    const int tx  = tid & 15;        // 0..15  -> col group
    const int ty  = tid >> 4;        // 0..15  -> row group
    const int r0  = blockIdx.y * BM;
    const int c0  = blockIdx.x * BN;

    float acc[TM][TN];
    #pragma unroll
    for (int i = 0; i < TM; i++)
        #pragma unroll
        for (int j = 0; j < TN; j++)
            acc[i][j] = 0.0f;

    for (int k0 = 0; k0 < D; k0 += BK) {
        // ---- load 128x16 A tile and 128x16 B tile (both from x), transposed into smem
        #pragma unroll
        for (int l = 0; l < 2; l++) {
            int idx = tid + l * 256;         // 0..511
            int row = idx >> 2;              // 0..127
            int c   = idx & 3;               // which float4 within the 16-wide k slab
            float4 va = *reinterpret_cast<const float4*>(
                &x[(size_t)(r0 + row) * D + k0 + c * 4]);
            As[c*4 + 0][row] = va.x;
            As[c*4 + 1][row] = va.y;
            As[c*4 + 2][row] = va.z;
            As[c*4 + 3][row] = va.w;
            float4 vb = *reinterpret_cast<const float4*>(
                &x[(size_t)(c0 + row) * D + k0 + c * 4]);
            Bs[c*4 + 0][row] = vb.x;
            Bs[c*4 + 1][row] = vb.y;
            Bs[c*4 + 2][row] = vb.z;
            Bs[c*4 + 3][row] = vb.w;
        }
        __syncthreads();

        #pragma unroll
        for (int kk = 0; kk < BK; kk++) {
            float a[TM], b[TN];
            #pragma unroll
            for (int i = 0; i < TM; i += 4) {
                float4 v = *reinterpret_cast<const float4*>(&As[kk][ty * TM + i]);
                a[i+0] = v.x; a[i+1] = v.y; a[i+2] = v.z; a[i+3] = v.w;
            }
            #pragma unroll
            for (int j = 0; j < TN; j += 4) {
                float4 v = *reinterpret_cast<const float4*>(&Bs[kk][tx * TN + j]);
                b[j+0] = v.x; b[j+1] = v.y; b[j+2] = v.z; b[j+3] = v.w;
            }
            #pragma unroll
            for (int i = 0; i < TM; i++)
                #pragma unroll
                for (int j = 0; j < TN; j++)
                    acc[i][j] = fmaf(a[i], b[j], acc[i][j]);
        }
        __syncthreads();
    }

    // ---- fused epilogue ----
    const float thr = *thr_p;
    const float tv  = *t_p;

    float sqi[TM], sqj[TN];
    #pragma unroll
    for (int i = 0; i < TM; i++) sqi[i] = g_sq[r0 + ty * TM + i];
    #pragma unroll
    for (int j = 0; j < TN; j++) sqj[j] = g_sq[c0 + tx * TN + j];

    #pragma unroll
    for (int i = 0; i < TM; i++) {
        #pragma unroll
        for (int j = 0; j < TN; j++) {
            float d2 = sqi[i] + sqj[j] - 2.0f * acc[i][j];
            d2 = fmaxf(d2, EPS);
            float z = (sqrtf(d2) + thr) * tv;
            // out = 1 - sigmoid(z); formulated so large z rounds to exactly 0.0,
            // matching the reference's fp32 rounding behavior.
            float s = 1.0f / (1.0f + __expf(-z));
            acc[i][j] = 1.0f - s;
        }
        int row = r0 + ty * TM + i;
        float4* o = reinterpret_cast<float4*>(&out[(size_t)row * N + c0 + tx * TN]);
        o[0] = make_float4(acc[i][0], acc[i][1], acc[i][2], acc[i][3]);
        o[1] = make_float4(acc[i][4], acc[i][5], acc[i][6], acc[i][7]);
    }
}

// ---------------------------------------------------------------------------
extern "C" void kernel_launch(void* const* d_in, const int* in_sizes, int n_in,
                              void* d_out, int out_size) {
    const float* x   = (const float*)d_in[0];
    const float* thr = (const float*)d_in[1];
    const float* t   = (const float*)d_in[2];
    float* out = (float*)d_out;

    // Kernel 1: row norms (8192 rows, 8 warps/block)
    row_sq_kernel<<<N / 8, 256>>>(x);

    // Kernel 2: fused distance + sigmoid GEMM
    dim3 grid(N / BN, N / BM);
    dist_sigmoid_kernel<<<grid, 256>>>(x, thr, t, out);
}

// round 5
// speedup vs baseline: 4.8216x; 4.8216x over previous
#include <cuda_runtime.h>
#include <cuda_bf16.h>
#include <math.h>
#include <stdint.h>

// Problem constants
constexpr int N = 8192;
constexpr int D = 256;
constexpr float EPS = 1e-12f;

// GEMM tiling
constexpr int BM = 128;
constexpr int BN = 128;
constexpr int BK = 64;                       // k-chunk held in smem per stage
constexpr int STAGE_BYTES = BM * BK * 2;     // 16384 per operand per stage
constexpr int DYN_SMEM = 4 * STAGE_BYTES;    // A0,A1,B0,B1 = 64KB

// Scratch (allocation-free rule -> __device__ globals)
__device__ float g_sq[N];
__device__ __align__(16) __nv_bfloat16 g_xb[N * D];

// ---------------------------------------------------------------------------
// helpers
// ---------------------------------------------------------------------------
__device__ __forceinline__ uint32_t smem_u32(const void* p) {
    uint32_t a;
    asm("{ .reg .u64 t; cvta.to.shared.u64 t, %1; cvt.u32.u64 %0, t; }" : "=r"(a) : "l"(p));
    return a;
}

__device__ __forceinline__ void ldsm_x4(uint32_t* r, uint32_t addr) {
    asm volatile("ldmatrix.sync.aligned.m8n8.x4.shared.b16 {%0,%1,%2,%3}, [%4];"
                 : "=r"(r[0]), "=r"(r[1]), "=r"(r[2]), "=r"(r[3]) : "r"(addr));
}

__device__ __forceinline__ void mma_16816(float* c, const uint32_t* a, const uint32_t* b) {
    asm volatile(
        "mma.sync.aligned.m16n8k16.row.col.f32.bf16.bf16.f32 "
        "{%0,%1,%2,%3}, {%4,%5,%6,%7}, {%8,%9}, {%0,%1,%2,%3};"
        : "+f"(c[0]), "+f"(c[1]), "+f"(c[2]), "+f"(c[3])
        : "r"(a[0]), "r"(a[1]), "r"(a[2]), "r"(a[3]), "r"(b[0]), "r"(b[1]));
}

__device__ __forceinline__ float fast_sqrt(float x) {
    float r;
    asm("sqrt.approx.f32 %0, %1;" : "=f"(r) : "f"(x));
    return r;
}

__device__ __forceinline__ float gate(float d2raw, float thr, float tv) {
    float d2 = fmaxf(d2raw, EPS);
    float z  = (fast_sqrt(d2) + thr) * tv;
    float e  = __expf(-z);
    // 1 - 1/(1+e): rounds to exactly 0.0 for large z, matching reference fp32 rounding
    return 1.0f - __fdividef(1.0f, 1.0f + e);
}

// ---------------------------------------------------------------------------
// Kernel 1: per-row squared norm (fp32) + fp32 -> bf16 conversion, 1 warp/row
// ---------------------------------------------------------------------------
__global__ void prep_kernel(const float* __restrict__ x) {
    int row  = blockIdx.x * 8 + (threadIdx.x >> 5);
    int lane = threadIdx.x & 31;
    const float4* p = reinterpret_cast<const float4*>(x + (size_t)row * D);
    float4 a = p[lane];
    float4 b = p[lane + 32];
    float s = a.x*a.x + a.y*a.y + a.z*a.z + a.w*a.w
            + b.x*b.x + b.y*b.y + b.z*b.z + b.w*b.w;
    #pragma unroll
    for (int off = 16; off > 0; off >>= 1)
        s += __shfl_xor_sync(0xffffffffu, s, off);
    if (lane == 0) g_sq[row] = s;

    uint32_t* dst = reinterpret_cast<uint32_t*>(g_xb + (size_t)row * D);
    __nv_bfloat162 h0 = __floats2bfloat162_rn(a.x, a.y);
    __nv_bfloat162 h1 = __floats2bfloat162_rn(a.z, a.w);
    __nv_bfloat162 h2 = __floats2bfloat162_rn(b.x, b.y);
    __nv_bfloat162 h3 = __floats2bfloat162_rn(b.z, b.w);
    dst[lane*2 + 0]      = *reinterpret_cast<uint32_t*>(&h0);
    dst[lane*2 + 1]      = *reinterpret_cast<uint32_t*>(&h1);
    dst[64 + lane*2 + 0] = *reinterpret_cast<uint32_t*>(&h2);
    dst[64 + lane*2 + 1] = *reinterpret_cast<uint32_t*>(&h3);
}

// ---------------------------------------------------------------------------
// Kernel 2: bf16 mma.sync GEMM (128x128 tile, warp 64x32) + fused epilogue
// smem: 128B rows (64 bf16), XOR swizzle off ^= (off>>3)&0x70 -> conflict-free
// ldmatrix for both operands (TN layout, no .trans).
// ---------------------------------------------------------------------------
__global__ void __launch_bounds__(256, 2)
gemm_kernel(const float* __restrict__ thr_p, const float* __restrict__ t_p,
            float* __restrict__ out)
{
    extern __shared__ char smem[];
    const uint32_t smem_base = smem_u32(smem);

    const int tid  = threadIdx.x;
    const int wid  = tid >> 5;
    const int lane = tid & 31;
    const int wm   = wid >> 2;            // 0..1 : 64-row slab
    const int wn   = wid & 3;             // 0..3 : 32-col slab
    const int r0   = blockIdx.y * BM;
    const int c0   = blockIdx.x * BN;

    const char* gA = reinterpret_cast<const char*>(g_xb) + (size_t)r0 * D * 2;
    const char* gB = reinterpret_cast<const char*>(g_xb) + (size_t)c0 * D * 2;

    // ---- async stage loader: 1024 x 16B chunks per operand per stage ----
    auto load_stage = [&](int kc, int buf) {
        uint32_t sA = smem_base + buf * STAGE_BYTES;
        uint32_t sB = smem_base + 2 * STAGE_BYTES + buf * STAGE_BYTES;
        #pragma unroll
        for (int i = 0; i < 4; i++) {
            int idx = tid + i * 256;          // 0..1023
            int row = idx >> 3;               // 0..127
            int c8  = idx & 7;                // 16B chunk within 128B row
            uint32_t off = (uint32_t)row * 128u + (uint32_t)c8 * 16u;
            off ^= (off >> 3) & 0x70u;
            const char* ga = gA + (size_t)row * 512 + kc * 128 + c8 * 16;
            const char* gb = gB + (size_t)row * 512 + kc * 128 + c8 * 16;
            asm volatile("cp.async.cg.shared.global [%0], [%1], 16;" :: "r"(sA + off), "l"(ga));
            asm volatile("cp.async.cg.shared.global [%0], [%1], 16;" :: "r"(sB + off), "l"(gb));
        }
    };

    float acc[4][4][4];
    #pragma unroll
    for (int mi = 0; mi < 4; mi++)
        #pragma unroll
        for (int ni = 0; ni < 4; ni++)
            #pragma unroll
            for (int q = 0; q < 4; q++) acc[mi][ni][q] = 0.0f;

    load_stage(0, 0);
    asm volatile("cp.async.commit_group;" ::: "memory");
    load_stage(1, 1);
    asm volatile("cp.async.commit_group;" ::: "memory");

    // ldmatrix lane address components
    const int a_lrow = lane & 15;          // row within 16-row tile
    const int a_k8   = lane >> 4;          // which 8-col k half
    const int b_lrow = ((lane >> 4) << 3) + (lane & 7);  // n row within 16
    const int b_k8   = (lane >> 3) & 1;

    for (int kc = 0; kc < 4; kc++) {
        if (kc < 3) asm volatile("cp.async.wait_group 1;" ::: "memory");
        else        asm volatile("cp.async.wait_group 0;" ::: "memory");
        __syncthreads();

        const int buf = kc & 1;
        const uint32_t sA = smem_base + buf * STAGE_BYTES;
        const uint32_t sB = smem_base + 2 * STAGE_BYTES + buf * STAGE_BYTES;

        #pragma unroll
        for (int ks = 0; ks < 4; ks++) {
            uint32_t aregs[4][4];
            #pragma unroll
            for (int mi = 0; mi < 4; mi++) {
                uint32_t off = (uint32_t)((wm * 64 + mi * 16 + a_lrow) * 128)
                             + (uint32_t)(ks * 32 + a_k8 * 16);
                off ^= (off >> 3) & 0x70u;
                ldsm_x4(aregs[mi], sA + off);
            }
            uint32_t bregs[8];
            #pragma unroll
            for (int h = 0; h < 2; h++) {
                uint32_t off = (uint32_t)((wn * 32 + h * 16 + b_lrow) * 128)
                             + (uint32_t)(ks * 32 + b_k8 * 16);
                off ^= (off >> 3) & 0x70u;
                ldsm_x4(&bregs[h * 4], sB + off);
            }
            // bregs: [h*4 + t*2 + {0,1}] = n-tile (h*2+t) frag {b0,b1}
            #pragma unroll
            for (int mi = 0; mi < 4; mi++)
                #pragma unroll
                for (int ni = 0; ni < 4; ni++)
                    mma_16816(acc[mi][ni], aregs[mi],
                              &bregs[(ni >> 1) * 4 + (ni & 1) * 2]);
        }

        __syncthreads();
        if (kc < 2) {
            load_stage(kc + 2, buf);
            asm volatile("cp.async.commit_group;" ::: "memory");
        }
    }

    // ---- fused epilogue ----
    const float thr = __ldg(thr_p);
    const float tv  = __ldg(t_p);

    const int rbase = r0 + wm * 64 + (lane >> 2);
    const int cbase = c0 + wn * 32 + 2 * (lane & 3);

    #pragma unroll
    for (int mi = 0; mi < 4; mi++) {
        int rt = rbase + mi * 16;
        float sq_t = __ldg(&g_sq[rt]);
        float sq_b = __ldg(&g_sq[rt + 8]);
        #pragma unroll
        for (int ni = 0; ni < 4; ni++) {
            int c = cbase + ni * 8;
            float sc0 = __ldg(&g_sq[c]);
            float sc1 = __ldg(&g_sq[c + 1]);
            float2 v0, v1;
            v0.x = gate(sq_t + sc0 - 2.0f * acc[mi][ni][0], thr, tv);
            v0.y = gate(sq_t + sc1 - 2.0f * acc[mi][ni][1], thr, tv);
            v1.x = gate(sq_b + sc0 - 2.0f * acc[mi][ni][2], thr, tv);
            v1.y = gate(sq_b + sc1 - 2.0f * acc[mi][ni][3], thr, tv);
            *reinterpret_cast<float2*>(&out[(size_t)rt * N + c])       = v0;
            *reinterpret_cast<float2*>(&out[(size_t)(rt + 8) * N + c]) = v1;
        }
    }
}

// ---------------------------------------------------------------------------
// Kernel 3: diagonal fixup in exact fp32, replicating round-1 arithmetic:
// sq from g_sq (shuffle-tree), dot via strictly ascending sequential fmaf.
// ---------------------------------------------------------------------------
__global__ void diag_kernel(const float* __restrict__ x,
                            const float* __restrict__ thr_p,
                            const float* __restrict__ t_p,
                            float* __restrict__ out) {
    int i = blockIdx.x * 256 + threadIdx.x;     // row index
    const float* xi = x + (size_t)i * D;
    float dot = 0.0f;
    #pragma unroll 8
    for (int k = 0; k < D; k++)
        dot = fmaf(xi[k], xi[k], dot);
    float sq = g_sq[i];
    float d2 = sq + sq - 2.0f * dot;
    d2 = fmaxf(d2, EPS);
    float z = (sqrtf(d2) + *thr_p) * (*t_p);
    float s = 1.0f / (1.0f + __expf(-z));
    out[(size_t)i * (N + 1)] = 1.0f - s;
}

// ---------------------------------------------------------------------------
extern "C" void kernel_launch(void* const* d_in, const int* in_sizes, int n_in,
                              void* d_out, int out_size) {
    const float* x   = (const float*)d_in[0];
    const float* thr = (const float*)d_in[1];
    const float* t   = (const float*)d_in[2];
    float* out = (float*)d_out;

    cudaFuncSetAttribute(gemm_kernel, cudaFuncAttributeMaxDynamicSharedMemorySize, DYN_SMEM);

    prep_kernel<<<N / 8, 256>>>(x);

    dim3 grid(N / BN, N / BM);   // 64 x 64
    gemm_kernel<<<grid, 256, DYN_SMEM>>>(thr, t, out);

    diag_kernel<<<N / 256, 256>>>(x, thr, t, out);
}

// round 7
// speedup vs baseline: 5.2294x; 1.0846x over previous
#include <cuda_runtime.h>
#include <cuda_bf16.h>
#include <math.h>
#include <stdint.h>

// Problem constants
constexpr int N = 8192;
constexpr int D = 256;
constexpr float EPS = 1e-12f;

// GEMM tiling
constexpr int BM = 128;
constexpr int BN = 128;
constexpr int NB = N / BM;                   // 64 tile-blocks per dim
constexpr int NTILES = NB * (NB + 1) / 2;    // 2080 upper-triangle tiles
constexpr int STAGE_BYTES = BM * 64 * 2;     // 16384 per operand per stage (BK=64)
constexpr int TSTRIDE = 132;                 // fp32 row stride of transpose buffer
constexpr int DYN_SMEM_GEMM = 4 * STAGE_BYTES;        // 64KB
constexpr int DYN_SMEM_TR   = BM * TSTRIDE * 4;       // 67584
constexpr int DYN_SMEM = (DYN_SMEM_TR > DYN_SMEM_GEMM) ? DYN_SMEM_TR : DYN_SMEM_GEMM;

// Scratch (allocation-free rule -> __device__ globals)
__device__ float g_sq[N];
__device__ __align__(16) __nv_bfloat16 g_xb[N * D];

// ---------------------------------------------------------------------------
// helpers
// ---------------------------------------------------------------------------
__device__ __forceinline__ uint32_t smem_u32(const void* p) {
    uint32_t a;
    asm("{ .reg .u64 t; cvta.to.shared.u64 t, %1; cvt.u32.u64 %0, t; }" : "=r"(a) : "l"(p));
    return a;
}

__device__ __forceinline__ void ldsm_x4(uint32_t* r, uint32_t addr) {
    asm volatile("ldmatrix.sync.aligned.m8n8.x4.shared.b16 {%0,%1,%2,%3}, [%4];"
                 : "=r"(r[0]), "=r"(r[1]), "=r"(r[2]), "=r"(r[3]) : "r"(addr));
}

__device__ __forceinline__ void mma_16816(float* c, const uint32_t* a, const uint32_t* b) {
    asm volatile(
        "mma.sync.aligned.m16n8k16.row.col.f32.bf16.bf16.f32 "
        "{%0,%1,%2,%3}, {%4,%5,%6,%7}, {%8,%9}, {%0,%1,%2,%3};"
        : "+f"(c[0]), "+f"(c[1]), "+f"(c[2]), "+f"(c[3])
        : "r"(a[0]), "r"(a[1]), "r"(a[2]), "r"(a[3]), "r"(b[0]), "r"(b[1]));
}

__device__ __forceinline__ float fast_sqrt(float x) {
    float r;
    asm("sqrt.approx.f32 %0, %1;" : "=f"(r) : "f"(x));
    return r;
}

__device__ __forceinline__ float gate(float d2raw, float thr, float tv) {
    float d2 = fmaxf(d2raw, EPS);
    float z  = (fast_sqrt(d2) + thr) * tv;
    float e  = __expf(-z);
    // 1 - 1/(1+e): rounds to exactly 0.0 for large z, matching reference fp32 rounding
    return 1.0f - __fdividef(1.0f, 1.0f + e);
}

// ---------------------------------------------------------------------------
// Kernel 1: per-row squared norm (fp32) + fp32 -> bf16 conversion, 1 warp/row
// ---------------------------------------------------------------------------
__global__ void prep_kernel(const float* __restrict__ x) {
    int row  = blockIdx.x * 8 + (threadIdx.x >> 5);
    int lane = threadIdx.x & 31;
    const float4* p = reinterpret_cast<const float4*>(x + (size_t)row * D);
    float4 a = p[lane];
    float4 b = p[lane + 32];
    float s = a.x*a.x + a.y*a.y + a.z*a.z + a.w*a.w
            + b.x*b.x + b.y*b.y + b.z*b.z + b.w*b.w;
    #pragma unroll
    for (int off = 16; off > 0; off >>= 1)
        s += __shfl_xor_sync(0xffffffffu, s, off);
    if (lane == 0) g_sq[row] = s;

    uint32_t* dst = reinterpret_cast<uint32_t*>(g_xb + (size_t)row * D);
    __nv_bfloat162 h0 = __floats2bfloat162_rn(a.x, a.y);
    __nv_bfloat162 h1 = __floats2bfloat162_rn(a.z, a.w);
    __nv_bfloat162 h2 = __floats2bfloat162_rn(b.x, b.y);
    __nv_bfloat162 h3 = __floats2bfloat162_rn(b.z, b.w);
    dst[lane*2 + 0]      = *reinterpret_cast<uint32_t*>(&h0);
    dst[lane*2 + 1]      = *reinterpret_cast<uint32_t*>(&h1);
    dst[64 + lane*2 + 0] = *reinterpret_cast<uint32_t*>(&h2);
    dst[64 + lane*2 + 1] = *reinterpret_cast<uint32_t*>(&h3);
}

// ---------------------------------------------------------------------------
// Kernel 2: bf16 mma.sync GEMM over upper-triangle tiles only + fused epilogue
// writing both the tile and its transpose (symmetric output).
// ---------------------------------------------------------------------------
__global__ void __launch_bounds__(256, 2)
gemm_kernel(const float* __restrict__ thr_p, const float* __restrict__ t_p,
            float* __restrict__ out)
{
    extern __shared__ char smem[];
    const uint32_t smem_base = smem_u32(smem);
    float* const smem_f = reinterpret_cast<float*>(smem);

    const int tid  = threadIdx.x;
    const int lane = tid & 31;
    const int wid  = tid >> 5;
    const int wm   = wid >> 2;            // 0..1 : 64-row slab
    const int wn   = wid & 3;             // 0..3 : 32-col slab

    // ---- decode upper-triangle tile index (bi <= bj) ----
    const int idx = blockIdx.x;
    const float f = 2.0f * NB + 1.0f;
    int bi = (int)((f - sqrtf(f * f - 8.0f * (float)idx)) * 0.5f);
    // S(b) = b*NB - b*(b-1)/2 ; fix rounding
    while ((bi + 1) * NB - ((bi + 1) * bi) / 2 <= idx) bi++;
    while (bi * NB - (bi * (bi - 1)) / 2 > idx) bi--;
    const int bj = bi + (idx - (bi * NB - (bi * (bi - 1)) / 2));
    const int r0 = bi * BM;
    const int c0 = bj * BN;

    const char* gA = reinterpret_cast<const char*>(g_xb) + (size_t)r0 * D * 2;
    const char* gB = reinterpret_cast<const char*>(g_xb) + (size_t)c0 * D * 2;

    // ---- async stage loader: 1024 x 16B chunks per operand per stage ----
    auto load_stage = [&](int kc, int buf) {
        uint32_t sA = smem_base + buf * STAGE_BYTES;
        uint32_t sB = smem_base + 2 * STAGE_BYTES + buf * STAGE_BYTES;
        #pragma unroll
        for (int i = 0; i < 4; i++) {
            int id2 = tid + i * 256;          // 0..1023
            int row = id2 >> 3;               // 0..127
            int c8  = id2 & 7;                // 16B chunk within 128B row
            uint32_t off = (uint32_t)row * 128u + (uint32_t)c8 * 16u;
            off ^= (off >> 3) & 0x70u;
            const char* ga = gA + (size_t)row * 512 + kc * 128 + c8 * 16;
            const char* gb = gB + (size_t)row * 512 + kc * 128 + c8 * 16;
            asm volatile("cp.async.cg.shared.global [%0], [%1], 16;" :: "r"(sA + off), "l"(ga));
            asm volatile("cp.async.cg.shared.global [%0], [%1], 16;" :: "r"(sB + off), "l"(gb));
        }
    };

    float acc[4][4][4];
    #pragma unroll
    for (int mi = 0; mi < 4; mi++)
        #pragma unroll
        for (int ni = 0; ni < 4; ni++)
            #pragma unroll
            for (int q = 0; q < 4; q++) acc[mi][ni][q] = 0.0f;

    load_stage(0, 0);
    asm volatile("cp.async.commit_group;" ::: "memory");
    load_stage(1, 1);
    asm volatile("cp.async.commit_group;" ::: "memory");

    const int a_lrow = lane & 15;
    const int a_k8   = lane >> 4;
    const int b_lrow = ((lane >> 4) << 3) + (lane & 7);
    const int b_k8   = (lane >> 3) & 1;

    for (int kc = 0; kc < 4; kc++) {
        if (kc < 3) asm volatile("cp.async.wait_group 1;" ::: "memory");
        else        asm volatile("cp.async.wait_group 0;" ::: "memory");
        __syncthreads();

        const int buf = kc & 1;
        const uint32_t sA = smem_base + buf * STAGE_BYTES;
        const uint32_t sB = smem_base + 2 * STAGE_BYTES + buf * STAGE_BYTES;

        #pragma unroll
        for (int ks = 0; ks < 4; ks++) {
            uint32_t aregs[4][4];
            #pragma unroll
            for (int mi = 0; mi < 4; mi++) {
                uint32_t off = (uint32_t)((wm * 64 + mi * 16 + a_lrow) * 128)
                             + (uint32_t)(ks * 32 + a_k8 * 16);
                off ^= (off >> 3) & 0x70u;
                ldsm_x4(aregs[mi], sA + off);
            }
            uint32_t bregs[8];
            #pragma unroll
            for (int h = 0; h < 2; h++) {
                uint32_t off = (uint32_t)((wn * 32 + h * 16 + b_lrow) * 128)
                             + (uint32_t)(ks * 32 + b_k8 * 16);
                off ^= (off >> 3) & 0x70u;
                ldsm_x4(&bregs[h * 4], sB + off);
            }
            #pragma unroll
            for (int mi = 0; mi < 4; mi++)
                #pragma unroll
                for (int ni = 0; ni < 4; ni++)
                    mma_16816(acc[mi][ni], aregs[mi],
                              &bregs[(ni >> 1) * 4 + (ni & 1) * 2]);
        }

        __syncthreads();
        if (kc < 2) {
            load_stage(kc + 2, buf);
            asm volatile("cp.async.commit_group;" ::: "memory");
        }
    }

    // ---- fused epilogue: direct tile write + (if off-diagonal) smem-staged
    //      transposed tile write ----
    const float thr = __ldg(thr_p);
    const float tv  = __ldg(t_p);
    const bool  offdiag = (bi != bj);

    const int lr0 = wm * 64 + (lane >> 2);       // local row base
    const int lc0 = wn * 32 + 2 * (lane & 3);    // local col base

    #pragma unroll
    for (int mi = 0; mi < 4; mi++) {
        int lr = lr0 + mi * 16;
        int rt = r0 + lr;
        float sq_t = __ldg(&g_sq[rt]);
        float sq_b = __ldg(&g_sq[rt + 8]);
        #pragma unroll
        for (int ni = 0; ni < 4; ni++) {
            int lc = lc0 + ni * 8;
            int c  = c0 + lc;
            float sc0 = __ldg(&g_sq[c]);
            float sc1 = __ldg(&g_sq[c + 1]);
            float2 v0, v1;
            v0.x = gate(sq_t + sc0 - 2.0f * acc[mi][ni][0], thr, tv);
            v0.y = gate(sq_t + sc1 - 2.0f * acc[mi][ni][1], thr, tv);
            v1.x = gate(sq_b + sc0 - 2.0f * acc[mi][ni][2], thr, tv);
            v1.y = gate(sq_b + sc1 - 2.0f * acc[mi][ni][3], thr, tv);
            *reinterpret_cast<float2*>(&out[(size_t)rt * N + c])       = v0;
            *reinterpret_cast<float2*>(&out[(size_t)(rt + 8) * N + c]) = v1;
            if (offdiag) {
                smem_f[(lc    ) * TSTRIDE + lr]     = v0.x;
                smem_f[(lc + 1) * TSTRIDE + lr]     = v0.y;
                smem_f[(lc    ) * TSTRIDE + lr + 8] = v1.x;
                smem_f[(lc + 1) * TSTRIDE + lr + 8] = v1.y;
            }
        }
    }

    if (offdiag) {
        __syncthreads();
        // write transpose tile at (c0.., r0..): 2 threads per row, 64 floats each
        const int row  = tid >> 1;               // 0..127 (local col -> global row c0+row)
        const int col0 = (tid & 1) * 64;
        const float4* src = reinterpret_cast<const float4*>(smem_f + row * TSTRIDE + col0);
        float4* dst = reinterpret_cast<float4*>(out + (size_t)(c0 + row) * N + r0 + col0);
        #pragma unroll
        for (int q = 0; q < 16; q++)
            dst[q] = src[q];
    }
}

// ---------------------------------------------------------------------------
// Kernel 3: diagonal fixup in exact fp32 (round-1 arithmetic).
// ---------------------------------------------------------------------------
__global__ void diag_kernel(const float* __restrict__ x,
                            const float* __restrict__ thr_p,
                            const float* __restrict__ t_p,
                            float* __restrict__ out) {
    int i = blockIdx.x * 256 + threadIdx.x;     // row index
    const float* xi = x + (size_t)i * D;
    float dot = 0.0f;
    #pragma unroll 8
    for (int k = 0; k < D; k++)
        dot = fmaf(xi[k], xi[k], dot);
    float sq = g_sq[i];
    float d2 = sq + sq - 2.0f * dot;
    d2 = fmaxf(d2, EPS);
    float z = (sqrtf(d2) + *thr_p) * (*t_p);
    float s = 1.0f / (1.0f + __expf(-z));
    out[(size_t)i * (N + 1)] = 1.0f - s;
}

// ---------------------------------------------------------------------------
extern "C" void kernel_launch(void* const* d_in, const int* in_sizes, int n_in,
                              void* d_out, int out_size) {
    const float* x   = (const float*)d_in[0];
    const float* thr = (const float*)d_in[1];
    const float* t   = (const float*)d_in[2];
    float* out = (float*)d_out;

    cudaFuncSetAttribute(gemm_kernel, cudaFuncAttributeMaxDynamicSharedMemorySize, DYN_SMEM);

    prep_kernel<<<N / 8, 256>>>(x);

    gemm_kernel<<<NTILES, 256, DYN_SMEM>>>(thr, t, out);

    diag_kernel<<<N / 256, 256>>>(x, thr, t, out);
}